// round 4
// baseline (speedup 1.0000x reference)
#include <cuda_runtime.h>

// ---------------------------------------------------------------------------
// QWTForward collapses to: D = bicubic_down2(image); out[q][b] = D * (S_a*S_b)
// where S_* are the sums of the 4 filter tap arrays (reference's filt(x,h)
// is exactly x * sum(h), and downsample is linear).
//
// CRITICAL: sum(gh), sum(fl), sum(fh) are analytically zero rounding residue;
// outputs 1-3 are proportional to it. Summation must be SEQUENTIAL per filter
// (matches jnp.sum rounding; verified passing R1/R3). Unrolling preserves the
// order while letting all loads issue in parallel (kills the R3 prologue
// serialization: 30x240cyc dependent L2 hits -> ~240cyc total).
//
// Main body: 4 consecutive output pixels per thread (shared horizontal taps,
// 40 loads / 4 px), 16 float4 stores per thread.
// ---------------------------------------------------------------------------

__global__ __launch_bounds__(256) void qwt_fused_kernel(
    const float* __restrict__ img,
    const float* __restrict__ gl, const float* __restrict__ gh,
    const float* __restrict__ fl, const float* __restrict__ fh,
    float* __restrict__ out, int NC, int L) {

    __shared__ float sc[16];

    // ---- per-block scale factors: sequential sums, parallel-issued loads ----
    if (threadIdx.x < 16) {
        const int t = threadIdx.x;
        const int q = t >> 2, b = t & 3;
        const int fi = ((b & 1) << 1) | (q >> 1);
        const int si = ((b >> 1) << 1) | (q & 1);
        const float* Ff = (fi == 0) ? gl : (fi == 1) ? gh : (fi == 2) ? fl : fh;
        const float* Fs = (si == 0) ? gl : (si == 1) ? gh : (si == 2) ? fl : fh;
        float sf = 0.f, ss = 0.f;
        if (L == 30) {
            float a[30], c[30];
#pragma unroll
            for (int i = 0; i < 30; i++) { a[i] = Ff[i]; c[i] = Fs[i]; }
#pragma unroll
            for (int i = 0; i < 30; i++) { sf += a[i]; ss += c[i]; }
        } else {
            for (int i = 0; i < L; i++) { sf += Ff[i]; ss += Fs[i]; }
        }
        sc[t] = sf * ss;
    }
    __syncthreads();

    // ---- main body: 4 consecutive output pixels of D per thread ----
    const unsigned idx = blockIdx.x * 256u + threadIdx.x;
    const unsigned xq = idx & 63u;           // x-quad: pixels 4*xq .. 4*xq+3
    const unsigned y  = (idx >> 6) & 255u;
    const unsigned nc = idx >> 14;

    const float* src = img + (size_t)nc * (512u * 512u);

    const float w0 = -0.09375f;
    const float w1 =  0.59375f;

    // input column indices: 8*xq-1 .. 8*xq+8, edge-clamped
    const int cbase = 8 * (int)xq - 1;
    int col[10];
#pragma unroll
    for (int k = 0; k < 10; k++) col[k] = min(max(cbase + k, 0), 511);

    const int yb = 2 * (int)y - 1;
    const int yr0 = max(yb, 0);
    const int yr3 = min(yb + 3, 511);
    const int yrow[4] = { yr0, yb + 1, yb + 2, yr3 };

    float h[4][4];
#pragma unroll
    for (int r = 0; r < 4; r++) {
        const float* rp = src + (size_t)yrow[r] * 512;
        float c0 = __ldg(rp + col[0]), c1 = __ldg(rp + col[1]);
        float c2 = __ldg(rp + col[2]), c3 = __ldg(rp + col[3]);
        float c4 = __ldg(rp + col[4]), c5 = __ldg(rp + col[5]);
        float c6 = __ldg(rp + col[6]), c7 = __ldg(rp + col[7]);
        float c8 = __ldg(rp + col[8]), c9 = __ldg(rp + col[9]);
        h[r][0] = w0 * (c0 + c3) + w1 * (c1 + c2);
        h[r][1] = w0 * (c2 + c5) + w1 * (c3 + c4);
        h[r][2] = w0 * (c4 + c7) + w1 * (c5 + c6);
        h[r][3] = w0 * (c6 + c9) + w1 * (c7 + c8);
    }

    // exact reference vertical combine: w0*(h0+h3) + w1*(h1+h2)
    float4 dv;
    dv.x = w0 * (h[0][0] + h[3][0]) + w1 * (h[1][0] + h[2][0]);
    dv.y = w0 * (h[0][1] + h[3][1]) + w1 * (h[1][1] + h[2][1]);
    dv.z = w0 * (h[0][2] + h[3][2]) + w1 * (h[1][2] + h[2][2]);
    dv.w = w0 * (h[0][3] + h[3][3]) + w1 * (h[1][3] + h[2][3]);

    const unsigned n = nc / 3u;
    const unsigned c = nc - 3u * n;
    const size_t plane = 256u * 256u;
    const size_t base  = ((size_t)(n * 12u + c)) * plane + (size_t)y * 256u + 4u * xq;
    const size_t QS    = (size_t)(NC / 3) * 12u * plane;  // elements per output tensor

    const float4* scv = (const float4*)sc;
#pragma unroll
    for (int q = 0; q < 4; q++) {
        const float4 sv = scv[q];
        float* o = out + base + (size_t)q * QS;
        *(float4*)(o)             = make_float4(dv.x * sv.x, dv.y * sv.x, dv.z * sv.x, dv.w * sv.x);
        *(float4*)(o + 3 * plane) = make_float4(dv.x * sv.y, dv.y * sv.y, dv.z * sv.y, dv.w * sv.y);
        *(float4*)(o + 6 * plane) = make_float4(dv.x * sv.z, dv.y * sv.z, dv.z * sv.z, dv.w * sv.z);
        *(float4*)(o + 9 * plane) = make_float4(dv.x * sv.w, dv.y * sv.w, dv.z * sv.w, dv.w * sv.w);
    }
}

extern "C" void kernel_launch(void* const* d_in, const int* in_sizes, int n_in,
                              void* d_out, int out_size) {
    const float* img = (const float*)d_in[0];
    const float* gl  = (const float*)d_in[1];
    const float* gh  = (const float*)d_in[2];
    const float* fl  = (const float*)d_in[3];
    const float* fh  = (const float*)d_in[4];

    const int L  = in_sizes[1];                 // filter length (30)
    const int NC = in_sizes[0] / (512 * 512);   // N*3 = 48 channels

    const int total_threads = NC * 256 * 256 / 4;   // 4 px per thread
    qwt_fused_kernel<<<total_threads / 256, 256>>>(img, gl, gh, fl, fh,
                                                   (float*)d_out, NC, L);
}

// round 5
// speedup vs baseline: 1.1035x; 1.1035x over previous
#include <cuda_runtime.h>

// ---------------------------------------------------------------------------
// QWTForward collapses to: D = bicubic_down2(image); out[q][b] = D * (S_a*S_b)
// where S_* are the sums of the 4 filter tap arrays (reference's filt(x,h)
// is exactly x * sum(h), and downsample is linear).
//
// CRITICAL: sum(gh), sum(fl), sum(fh) are analytically-zero rounding residue;
// outputs 1-3 are proportional to it. Summation must be SEQUENTIAL per filter
// (matches jnp.sum rounding; verified R1/R3/R4). The unrolled form keeps the
// add order but issues all 30 loads in parallel (~700cyc vs 7200 serialized).
//
// Body = R1's measured-best: 1 output pixel per thread, one y-row per block,
// plain coalesced scalar stores. Center taps (2x, 2x+1) fetched as one
// aligned float2 (12 loads/thread instead of 16).
// ---------------------------------------------------------------------------

__global__ __launch_bounds__(256) void qwt_fused_kernel(
    const float* __restrict__ img,
    const float* __restrict__ gl, const float* __restrict__ gh,
    const float* __restrict__ fl, const float* __restrict__ fh,
    float* __restrict__ out, int NC, int L) {

    __shared__ float sc[16];

    // ---- scale factors: sequential add order, parallel-issued loads ----
    if (threadIdx.x < 16) {
        const int t = threadIdx.x;
        const int q = t >> 2, b = t & 3;
        const int fi = ((b & 1) << 1) | (q >> 1);
        const int si = ((b >> 1) << 1) | (q & 1);
        const float* Ff = (fi == 0) ? gl : (fi == 1) ? gh : (fi == 2) ? fl : fh;
        const float* Fs = (si == 0) ? gl : (si == 1) ? gh : (si == 2) ? fl : fh;
        float sf = 0.f, ss = 0.f;
        if (L == 30) {
            float a[30], c[30];
#pragma unroll
            for (int i = 0; i < 30; i++) { a[i] = __ldg(Ff + i); c[i] = __ldg(Fs + i); }
#pragma unroll
            for (int i = 0; i < 30; i++) { sf += a[i]; ss += c[i]; }
        } else {
            for (int i = 0; i < L; i++) { sf += Ff[i]; ss += Fs[i]; }
        }
        sc[t] = sf * ss;
    }
    __syncthreads();

    // ---- main body: one output pixel of D per thread (R1 layout) ----
    const unsigned idx = blockIdx.x * 256u + threadIdx.x;
    const unsigned x  = idx & 255u;
    const unsigned y  = (idx >> 8) & 255u;
    const unsigned nc = idx >> 16;

    const float* src = img + (size_t)nc * (512u * 512u);

    const float w0 = -0.09375f;
    const float w1 =  0.59375f;

    const int xc = 2 * (int)x;              // center pair (xc, xc+1) — aligned float2
    const int x0 = max(xc - 1, 0);
    const int x3 = min(xc + 2, 511);

    const int yb = 2 * (int)y - 1;
    const int y0 = max(yb, 0);
    const int y3 = min(yb + 3, 511);

    const float* r0 = src + (size_t)y0 * 512;
    const float* r1 = src + (size_t)(yb + 1) * 512;
    const float* r2 = src + (size_t)(yb + 2) * 512;
    const float* r3 = src + (size_t)y3 * 512;

    const float2 m0 = __ldg((const float2*)(r0 + xc));
    const float2 m1 = __ldg((const float2*)(r1 + xc));
    const float2 m2 = __ldg((const float2*)(r2 + xc));
    const float2 m3 = __ldg((const float2*)(r3 + xc));

    float h0 = w0 * (__ldg(r0 + x0) + __ldg(r0 + x3)) + w1 * (m0.x + m0.y);
    float h1 = w0 * (__ldg(r1 + x0) + __ldg(r1 + x3)) + w1 * (m1.x + m1.y);
    float h2 = w0 * (__ldg(r2 + x0) + __ldg(r2 + x3)) + w1 * (m2.x + m2.y);
    float h3 = w0 * (__ldg(r3 + x0) + __ldg(r3 + x3)) + w1 * (m3.x + m3.y);

    const float dval = w0 * (h0 + h3) + w1 * (h1 + h2);

    const unsigned n = nc / 3u;
    const unsigned c = nc - 3u * n;
    const size_t plane = 256u * 256u;
    const size_t base  = ((size_t)(n * 12u + c)) * plane + (size_t)y * 256u + x;
    const size_t QS    = (size_t)(NC / 3) * 12u * plane;  // elements per output tensor

    const float4* scv = (const float4*)sc;
#pragma unroll
    for (int q = 0; q < 4; q++) {
        const float4 sv = scv[q];
        float* o = out + base + (size_t)q * QS;
        o[0]         = dval * sv.x;
        o[3 * plane] = dval * sv.y;
        o[6 * plane] = dval * sv.z;
        o[9 * plane] = dval * sv.w;
    }
}

extern "C" void kernel_launch(void* const* d_in, const int* in_sizes, int n_in,
                              void* d_out, int out_size) {
    const float* img = (const float*)d_in[0];
    const float* gl  = (const float*)d_in[1];
    const float* gh  = (const float*)d_in[2];
    const float* fl  = (const float*)d_in[3];
    const float* fh  = (const float*)d_in[4];

    const int L  = in_sizes[1];                 // filter length (30)
    const int NC = in_sizes[0] / (512 * 512);   // N*3 = 48 channels

    const int total_threads = NC * 256 * 256;   // one per downsampled pixel
    qwt_fused_kernel<<<total_threads / 256, 256>>>(img, gl, gh, fl, fh,
                                                   (float*)d_out, NC, L);
}